// round 1
// baseline (speedup 1.0000x reference)
#include <cuda_runtime.h>
#include <cuda_bf16.h>

typedef unsigned long long u64;

#define NBH 1024   // B*H
#define TT  4
#define DK  128
#define DV  256

// ---- packed f32x2 helpers (Blackwell sm_103a) ----
__device__ __forceinline__ u64 pk2(float x, float y){
    u64 r; asm("mov.b64 %0, {%1,%2};" : "=l"(r) : "f"(x), "f"(y)); return r;
}
__device__ __forceinline__ u64 fma2(u64 a, u64 b, u64 c){
    u64 d; asm("fma.rn.f32x2 %0, %1, %2, %3;" : "=l"(d) : "l"(a), "l"(b), "l"(c)); return d;
}
__device__ __forceinline__ u64 add2(u64 a, u64 b){
    u64 d; asm("add.rn.f32x2 %0, %1, %2;" : "=l"(d) : "l"(a), "l"(b)); return d;
}
__device__ __forceinline__ u64 mul2(u64 a, u64 b){
    u64 d; asm("mul.rn.f32x2 %0, %1, %2;" : "=l"(d) : "l"(a), "l"(b)); return d;
}

// One CTA handles one (b,h) pair and one half (128 cols) of Dv.
// Thread tid: cg = tid&31 -> 4 consecutive columns; rg = tid>>5 -> 16 rows.
// State slice (16 rows x 4 cols) lives in registers as 16 x ulonglong2
// (2 packed f32 pairs each) for the whole T=4 loop.
// Decay is factored out: state = c * S', c = prod exp(g_t). This removes the
// per-step full-state decay sweep; scaling folds into the scalar epilogues.
__global__ __launch_bounds__(256, 2)
void gdn_step_kernel(const float* __restrict__ q, const float* __restrict__ k,
                     const float* __restrict__ v, const float* __restrict__ g,
                     const float* __restrict__ beta, const float* __restrict__ s0,
                     float* __restrict__ out, float* __restrict__ sout)
{
    const int bh    = blockIdx.x >> 1;
    const int half  = blockIdx.x & 1;
    const int vbase = half * 128;
    const int tid   = threadIdx.x;
    const int cg    = tid & 31;   // column group (4 cols)
    const int rg    = tid >> 5;   // row group (16 rows)
    const int k0    = rg * 16;
    const int v0    = vbase + cg * 4;

    __shared__ __align__(16) float qs[TT * DK];
    __shared__ __align__(16) float ks[TT * DK];
    __shared__ __align__(16) float vs[TT * 128];
    __shared__ float gs[TT], bs[TT];
    __shared__ ulonglong2 red1[256];
    __shared__ ulonglong2 red2[256];

    // ---- front-batched state load: 16 x LDG.128, fully coalesced ----
    const size_t sbase = (size_t)bh * (DK * DV);
    ulonglong2 S[16];
#pragma unroll
    for (int kk = 0; kk < 16; kk++)
        S[kk] = *(const ulonglong2*)(s0 + sbase + (size_t)(k0 + kk) * DV + v0);

    // ---- stage q/k/v/g/beta for this (b,h) into smem ----
    {
        const int qb = bh * (TT * DK);
        for (int i = tid; i < TT * DK; i += 256){ qs[i] = q[qb + i]; ks[i] = k[qb + i]; }
        const int vb = bh * (TT * DV);
        for (int i = tid; i < TT * 128; i += 256){
            int t = i >> 7, j = i & 127;
            vs[i] = v[vb + t * DV + vbase + j];
        }
        if (tid < TT){ gs[tid] = g[bh * TT + tid]; bs[tid] = beta[bh * TT + tid]; }
    }
    __syncthreads();

    float c = 1.0f;   // cumulative decay; true state = c * S
#pragma unroll
    for (int t = 0; t < TT; t++){
        c *= __expf(gs[t]);

        // kv_mem partial: sum over this thread's 16 rows of S'[k][v] * k_t[k]
        u64 ax = 0ull, ay = 0ull;
#pragma unroll
        for (int kk = 0; kk < 16; kk++){
            float ktf = ks[t * DK + k0 + kk];
            u64 kt2 = pk2(ktf, ktf);
            ax = fma2(S[kk].x, kt2, ax);
            ay = fma2(S[kk].y, kt2, ay);
        }
        red1[tid] = make_ulonglong2(ax, ay);
        __syncthreads();

        // reduce 8 row-group partials (all threads need delta for their cols)
        u64 sx = 0ull, sy = 0ull;
#pragma unroll
        for (int r = 0; r < 8; r++){
            ulonglong2 p = red1[r * 32 + cg];
            sx = add2(sx, p.x); sy = add2(sy, p.y);
        }

        // delta = (v_t - c*kv_sum) * beta;  ds = delta / c (update of S')
        ulonglong2 vv = *(const ulonglong2*)&vs[t * 128 + cg * 4];
        u64 nc2 = pk2(-c, -c);
        u64 b2  = pk2(bs[t], bs[t]);
        u64 dx = mul2(fma2(sx, nc2, vv.x), b2);
        u64 dy = mul2(fma2(sy, nc2, vv.y), b2);
        float ic = 1.0f / c;
        u64 ic2 = pk2(ic, ic);
        dx = mul2(dx, ic2); dy = mul2(dy, ic2);

        // fused rank-1 update + q-readout partial
        u64 ox = 0ull, oy = 0ull;
#pragma unroll
        for (int kk = 0; kk < 16; kk++){
            float ktf = ks[t * DK + k0 + kk];
            u64 kt2 = pk2(ktf, ktf);
            S[kk].x = fma2(kt2, dx, S[kk].x);
            S[kk].y = fma2(kt2, dy, S[kk].y);
            float qtf = qs[t * DK + k0 + kk];
            u64 qt2 = pk2(qtf, qtf);
            ox = fma2(S[kk].x, qt2, ox);
            oy = fma2(S[kk].y, qt2, oy);
        }
        red2[tid] = make_ulonglong2(ox, oy);
        __syncthreads();

        if (rg == 0){
            u64 tx = 0ull, ty = 0ull;
#pragma unroll
            for (int r = 0; r < 8; r++){
                ulonglong2 p = red2[r * 32 + cg];
                tx = add2(tx, p.x); ty = add2(ty, p.y);
            }
            u64 c2 = pk2(c, c);
            ulonglong2 o; o.x = mul2(tx, c2); o.y = mul2(ty, c2);
            *(ulonglong2*)(out + (size_t)(bh * TT + t) * DV + v0) = o;
        }
    }

    // ---- final state writeback: state = c * S', 16 x STG.128 coalesced ----
    u64 c2 = pk2(c, c);
#pragma unroll
    for (int kk = 0; kk < 16; kk++){
        ulonglong2 w;
        w.x = mul2(S[kk].x, c2);
        w.y = mul2(S[kk].y, c2);
        *(ulonglong2*)(sout + sbase + (size_t)(k0 + kk) * DV + v0) = w;
    }
}

extern "C" void kernel_launch(void* const* d_in, const int* in_sizes, int n_in,
                              void* d_out, int out_size)
{
    const float* q    = (const float*)d_in[0];
    const float* k    = (const float*)d_in[1];
    const float* v    = (const float*)d_in[2];
    const float* g    = (const float*)d_in[3];
    const float* beta = (const float*)d_in[4];
    const float* s0   = (const float*)d_in[5];
    float* out  = (float*)d_out;
    float* sout = out + (size_t)NBH * TT * DV;   // state follows the T outputs

    gdn_step_kernel<<<NBH * 2, 256>>>(q, k, v, g, beta, s0, out, sout);
}